// round 4
// baseline (speedup 1.0000x reference)
#include <cuda_runtime.h>
#include <math_constants.h>

#define TT 50
#define TR 48
#define SSTART 48
#define SSTOP 49
#define LL 512
#define BB 1024
#define NTH 64

__device__ __forceinline__ unsigned long long pack2f(float a, float b) {
    unsigned long long u;
    asm("mov.b64 %0, {%1, %2};" : "=l"(u) : "f"(a), "f"(b));
    return u;
}
__device__ __forceinline__ void unpack2f(unsigned long long u, float& a, float& b) {
    asm("mov.b64 {%0, %1}, %2;" : "=f"(a), "=f"(b) : "l"(u));
}
// d = a*b + d, packed 2xf32 (Blackwell FFMA2)
__device__ __forceinline__ void fma2(unsigned long long& d,
                                     unsigned long long a, unsigned long long b) {
    asm("fma.rn.f32x2 %0, %1, %2, %0;" : "+l"(d) : "l"(a), "l"(b));
}
__device__ __forceinline__ float frcp(float x) {
    float r;
    asm("rcp.approx.f32 %0, %1;" : "=f"(r) : "f"(x));
    return r;
}

__global__ void zero_out_k(float* o) {
    if (threadIdx.x == 0) o[0] = 0.0f;
}

__global__ __launch_bounds__(NTH) void crf_nll_kernel(
    const float* __restrict__ logits,   // [B, L, T]
    const float* __restrict__ trans,    // [T, T]
    const int*   __restrict__ labels,   // [B, L]
    const int*   __restrict__ lens,     // [B]
    float* __restrict__ out)            // scalar
{
    const int b = blockIdx.x;
    const int j = threadIdx.x;

    __shared__ __align__(16) float w_s[2 * TR];   // double-buffered scaled alphas
    __shared__ int   lab_s[LL];
    __shared__ float score_s;
    __shared__ float sum_s[2];

    const int len = lens[b];
    const float* lrow  = logits + (long)b * (LL * TT);
    const int*  labrow = labels + (long)b * LL;

    unsigned long long M2[TR / 2];
    float w = 0.0f, C = 0.0f, eStop = 0.0f, el = 0.0f;

    if (j < TR) {
        // ---- recursion lanes: M row (exp of transitions) + scaled alpha init.
        // START row / STOP column are -1e4 -> exp underflows to exactly 0,
        // identical to the reference's logsumexp, so both degenerate states
        // are dropped from the 48-state recursion.
        const float* trow = trans + j * TT;
        #pragma unroll
        for (int i = 0; i < TR / 2; ++i)
            M2[i] = pack2f(__expf(trow[2 * i]), __expf(trow[2 * i + 1]));
        eStop = __expf(trans[SSTOP * TT + j]);
        // t = 0: alpha0 = logit0 + trans[j, START]; w = exp(alpha0), C = 0
        w = __expf(lrow[j] + trow[SSTART]);
        w_s[j] = w;
        // prefetch logit(t=1) and its exp (consumed next step, off-path)
        el = __expf((1 < len) ? lrow[TT + j] : 0.0f);
    } else {
        // ---- scoring lanes (16): gold-path emission + transition score,
        // fully parallel, done before the recursion starts.
        const int s = j - 48;
        for (int t = s; t < len; t += 16) lab_s[t] = labrow[t];   // coalesced
        __syncwarp(0xFFFF0000u);
        float em = 0.0f, tr = 0.0f;
        #pragma unroll 4
        for (int t = s; t < len; t += 16) {
            int lb = lab_s[t];
            em += lrow[t * TT + lb];
            if (t > 0) tr += trans[lb * TT + lab_s[t - 1]];
        }
        if (s == 0)
            tr += trans[lab_s[0] * TT + SSTART] + trans[SSTOP * TT + lab_s[len - 1]];
        float sc = em + tr;
        #pragma unroll
        for (int d = 8; d >= 1; d >>= 1)
            sc += __shfl_xor_sync(0xFFFF0000u, sc, d);
        if (s == 0) score_s = sc;
    }
    __syncthreads();

    // ---- scaled forward recursion: w' = e^{lg} * (M_j . w) / sum(w).
    // sum(w) is computed locally by every lane from identical smem reads
    // (bit-identical -> block-uniform scale, no broadcast needed).
    const unsigned long long ONE2 = pack2f(1.0f, 1.0f);
    int p = 0;
    for (int t = 1; t < len; ++t) {
        float lg2 = 0.0f;
        if (j < TR && (t + 1) < len) lg2 = lrow[(t + 1) * TT + j];  // prefetch

        if (j < TR) {
            const ulonglong2* vv = reinterpret_cast<const ulonglong2*>(w_s + p * TR);
            unsigned long long a0 = 0, a1 = 0, a2 = 0, a3 = 0;
            unsigned long long s0 = 0, s1 = 0, s2 = 0, s3 = 0;
            #pragma unroll
            for (int i = 0; i < TR / 8; ++i) {
                ulonglong2 q0 = vv[2 * i];
                ulonglong2 q1 = vv[2 * i + 1];
                fma2(a0, M2[4 * i + 0], q0.x);
                fma2(a1, M2[4 * i + 1], q0.y);
                fma2(a2, M2[4 * i + 2], q1.x);
                fma2(a3, M2[4 * i + 3], q1.y);
                fma2(s0, ONE2, q0.x);
                fma2(s1, ONE2, q0.y);
                fma2(s2, ONE2, q1.x);
                fma2(s3, ONE2, q1.y);
            }
            float f0, f1, f2, f3, f4, f5, f6, f7;
            unpack2f(a0, f0, f1); unpack2f(a1, f2, f3);
            unpack2f(a2, f4, f5); unpack2f(a3, f6, f7);
            float S = ((f0 + f1) + (f2 + f3)) + ((f4 + f5) + (f6 + f7));
            float g0, g1, g2, g3, g4, g5, g6, g7;
            unpack2f(s0, g0, g1); unpack2f(s1, g2, g3);
            unpack2f(s2, g4, g5); unpack2f(s3, g6, g7);
            float sm = ((g0 + g1) + (g2 + g3)) + ((g4 + g5) + (g6 + g7));

            w = el * S * frcp(sm);          // critical path
            w_s[(p ^ 1) * TR + j] = w;
            C += __logf(sm);                // side chain (scale bookkeeping)
            el = __expf(lg2);               // for next step, off-path
        }
        __syncthreads();
        p ^= 1;
    }

    // ---- partition = C + log( sum_j w_j * exp(trans[STOP, j]) )
    float f = (j < TR) ? w * eStop : 0.0f;
    #pragma unroll
    for (int d = 16; d >= 1; d >>= 1)
        f += __shfl_xor_sync(0xFFFFFFFFu, f, d);
    if ((j & 31) == 0) sum_s[j >> 5] = f;
    __syncthreads();

    if (j == 0) {
        float part = C + __logf(sum_s[0] + sum_s[1]);
        atomicAdd(out, (part - score_s) * (1.0f / (float)BB));
    }
}

extern "C" void kernel_launch(void* const* d_in, const int* in_sizes, int n_in,
                              void* d_out, int out_size) {
    const float* logits = (const float*)d_in[0];
    const float* trans  = (const float*)d_in[1];
    const int*   labels = (const int*)d_in[2];
    const int*   lens   = (const int*)d_in[3];
    float* out = (float*)d_out;

    zero_out_k<<<1, 32>>>(out);
    crf_nll_kernel<<<BB, NTH>>>(logits, trans, labels, lens, out);
}

// round 5
// speedup vs baseline: 1.5221x; 1.5221x over previous
#include <cuda_runtime.h>
#include <math_constants.h>

#define TT 50
#define TR 48
#define SSTART 48
#define SSTOP 49
#define LL 512
#define BB 1024
#define NTH 64

__device__ __forceinline__ unsigned long long pack2f(float a, float b) {
    unsigned long long u;
    asm("mov.b64 %0, {%1, %2};" : "=l"(u) : "f"(a), "f"(b));
    return u;
}
__device__ __forceinline__ void unpack2f(unsigned long long u, float& a, float& b) {
    asm("mov.b64 {%0, %1}, %2;" : "=f"(a), "=f"(b) : "l"(u));
}
// d = a*b + d, packed 2xf32 (Blackwell FFMA2)
__device__ __forceinline__ void fma2(unsigned long long& d,
                                     unsigned long long a, unsigned long long b) {
    asm("fma.rn.f32x2 %0, %1, %2, %0;" : "+l"(d) : "l"(a), "l"(b));
}
__device__ __forceinline__ float frcp(float x) {
    float r;
    asm("rcp.approx.f32 %0, %1;" : "=f"(r) : "f"(x));
    return r;
}

__global__ void zero_out_k(float* o) {
    if (threadIdx.x == 0) o[0] = 0.0f;
}

__global__ __launch_bounds__(NTH) void crf_nll_kernel(
    const float* __restrict__ logits,   // [B, L, T]
    const float* __restrict__ trans,    // [T, T]
    const int*   __restrict__ labels,   // [B, L]
    const int*   __restrict__ lens,     // [B]
    float* __restrict__ out)            // scalar
{
    const int b = blockIdx.x;
    const int j = threadIdx.x;

    __shared__ __align__(16) float w_s[2 * TR];   // double-buffered scaled alphas
    __shared__ int   lab_s[LL];
    __shared__ float score_s;
    __shared__ float sum_s[2];

    const int len = lens[b];
    const float* lrow  = logits + (long)b * (LL * TT);
    const int*  labrow = labels + (long)b * LL;

    unsigned long long M2[TR / 2];
    float w = 0.0f, C = 0.0f, eStop = 0.0f, el = 0.0f;

    if (j < TR) {
        // ---- recursion lanes: M row (exp of transitions) + scaled alpha init.
        // START row / STOP column are -1e4 -> exp underflows to exactly 0,
        // matching the reference's logsumexp, so both degenerate states are
        // dropped from the 48-state recursion.
        const float* trow = trans + j * TT;
        #pragma unroll
        for (int i = 0; i < TR / 2; ++i)
            M2[i] = pack2f(__expf(trow[2 * i]), __expf(trow[2 * i + 1]));
        eStop = __expf(trans[SSTOP * TT + j]);
        // t = 0: w = exp(alpha0) = exp(logit0 + trans[j, START]), C = 0
        w = __expf(lrow[j] + trow[SSTART]);
        w_s[j] = w;
        // prefetch logit(t=1) and its exp (consumed next step, off-path)
        el = __expf((1 < len) ? lrow[TT + j] : 0.0f);
    } else {
        // ---- scoring lanes (16): gold-path emission + transition score,
        // fully parallel, done once before the recursion.
        const int s = j - 48;
        for (int t = s; t < len; t += 16) lab_s[t] = labrow[t];   // coalesced
        __syncwarp(0xFFFF0000u);
        float em = 0.0f, tr = 0.0f;
        #pragma unroll 4
        for (int t = s; t < len; t += 16) {
            int lb = lab_s[t];
            em += lrow[t * TT + lb];
            if (t > 0) tr += trans[lb * TT + lab_s[t - 1]];
        }
        if (s == 0)
            tr += trans[lab_s[0] * TT + SSTART] + trans[SSTOP * TT + lab_s[len - 1]];
        float sc = em + tr;
        #pragma unroll
        for (int d = 8; d >= 1; d >>= 1)
            sc += __shfl_xor_sync(0xFFFF0000u, sc, d);
        if (s == 0) score_s = sc;
    }
    __syncthreads();

    // ---- scaled forward recursion: w' = e^{lg} * (M_j . w) * rcp(w[0]).
    // w[0] (first element of the smem vector every thread already loads) is a
    // block-uniform normalizer obtained for FREE — no reduction, no broadcast.
    // rcp overlaps the FFMA2 chain; log(w0) accrues on an off-path side chain.
    int p = 0;
    for (int t = 1; t < len; ++t) {
        const int tn = (t + 1 < len) ? (t + 1) : t;       // clamped prefetch idx
        float lgN = (j < TR) ? lrow[tn * TT + j] : 0.0f;  // prefetch t+1

        if (j < TR) {
            const ulonglong2* vv = reinterpret_cast<const ulonglong2*>(w_s + p * TR);
            ulonglong2 q0 = vv[0];
            float w0, wdum;
            unpack2f(q0.x, w0, wdum);
            const float rn = frcp(w0);                    // MUFU, overlapped
            unsigned long long a0 = 0, a1 = 0, a2 = 0, a3 = 0;
            ulonglong2 q1 = vv[1];
            fma2(a0, M2[0], q0.x);
            fma2(a1, M2[1], q0.y);
            fma2(a2, M2[2], q1.x);
            fma2(a3, M2[3], q1.y);
            #pragma unroll
            for (int i = 1; i < TR / 8; ++i) {
                ulonglong2 r0 = vv[2 * i];
                ulonglong2 r1 = vv[2 * i + 1];
                fma2(a0, M2[4 * i + 0], r0.x);
                fma2(a1, M2[4 * i + 1], r0.y);
                fma2(a2, M2[4 * i + 2], r1.x);
                fma2(a3, M2[4 * i + 3], r1.y);
            }
            float f0, f1, f2, f3, f4, f5, f6, f7;
            unpack2f(a0, f0, f1); unpack2f(a1, f2, f3);
            unpack2f(a2, f4, f5); unpack2f(a3, f6, f7);
            const float S = ((f0 + f1) + (f2 + f3)) + ((f4 + f5) + (f6 + f7));

            w = el * S * rn;                 // critical path tail
            w_s[(p ^ 1) * TR + j] = w;
            C += __logf(w0);                 // off-path scale bookkeeping
            el = __expf(lgN);                // off-path, for next step
        }
        __syncthreads();
        p ^= 1;
    }

    // ---- partition = C + log( sum_j w_j * exp(trans[STOP, j]) )
    float f = (j < TR) ? w * eStop : 0.0f;
    #pragma unroll
    for (int d = 16; d >= 1; d >>= 1)
        f += __shfl_xor_sync(0xFFFFFFFFu, f, d);
    if ((j & 31) == 0) sum_s[j >> 5] = f;
    __syncthreads();

    if (j == 0) {
        float part = C + __logf(sum_s[0] + sum_s[1]);
        atomicAdd(out, (part - score_s) * (1.0f / (float)BB));
    }
}

extern "C" void kernel_launch(void* const* d_in, const int* in_sizes, int n_in,
                              void* d_out, int out_size) {
    const float* logits = (const float*)d_in[0];
    const float* trans  = (const float*)d_in[1];
    const int*   labels = (const int*)d_in[2];
    const int*   lens   = (const int*)d_in[3];
    float* out = (float*)d_out;

    zero_out_k<<<1, 32>>>(out);
    crf_nll_kernel<<<BB, NTH>>>(logits, trans, labels, lens, out);
}